// round 3
// baseline (speedup 1.0000x reference)
#include <cuda_runtime.h>
#include <cuda_bf16.h>
#include <stdint.h>

#define N_NODES 100000
#define N_EDGES 1600000
#define IN_CH   128
#define HID     64
#define OUT_CH  32

// ---------------- scratch (static device globals; no allocation) -------------
__device__ int   g_is64;
__device__ int   g_src[N_EDGES];
__device__ int   g_dst[N_EDGES];
__device__ int   g_deg[N_NODES];
__device__ float g_dinv[N_NODES];
__device__ int   g_rowoff[N_NODES + 1];
__device__ int   g_fill[N_NODES];
__device__ int   g_csr[N_EDGES];
__device__ int   g_partial[128];
__device__ float g_m1[(size_t)N_NODES * HID];
__device__ float g_h [(size_t)N_NODES * HID];
__device__ float g_m2[(size_t)N_NODES * OUT_CH];

// ---------------- dtype sniff + normalize ------------------------------------
// If edge_index is int64 (values in [0, N_NODES)), the high 32-bit word of every
// element is 0. For int32 data the odd positions are random values — the
// probability all 256 sampled are zero is ~0.
__global__ void detect_kernel(const int* __restrict__ ei32) {
    if (blockIdx.x == 0 && threadIdx.x == 0) {
        int ok64 = 1;
        for (int e = 0; e < 256; ++e) {
            if (ei32[2 * e + 1] != 0) { ok64 = 0; break; }
        }
        g_is64 = ok64;
    }
}

__global__ void convert_kernel(const int* __restrict__ ei32) {
    int e = blockIdx.x * blockDim.x + threadIdx.x;
    if (e >= N_EDGES) return;
    int s, d;
    if (g_is64) {
        s = ei32[2 * (size_t)e];
        d = ei32[2 * ((size_t)N_EDGES + e)];
    } else {
        s = ei32[e];
        d = ei32[(size_t)N_EDGES + e];
    }
    // clamp defensively (never triggers on valid data; keeps memory safe)
    if ((unsigned)s >= N_NODES) s = 0;
    if ((unsigned)d >= N_NODES) d = 0;
    g_src[e] = s;
    g_dst[e] = d;
}

// ---------------- small utility kernels --------------------------------------
__global__ void zero_counts_kernel() {
    int i = blockIdx.x * blockDim.x + threadIdx.x;
    if (i < N_NODES) { g_deg[i] = 0; g_fill[i] = 0; }
}

__global__ void count_deg_kernel() {
    int e = blockIdx.x * blockDim.x + threadIdx.x;
    if (e < N_EDGES) atomicAdd(&g_deg[g_dst[e]], 1);
}

__global__ void dinv_kernel() {
    int i = blockIdx.x * blockDim.x + threadIdx.x;
    if (i < N_NODES) g_dinv[i] = rsqrtf((float)(g_deg[i] + 1));  // +1 self-loop
}

// ---------------- exclusive scan of g_deg -> g_rowoff -------------------------
#define SCAN_CHUNK 1024
#define SCAN_NB ((N_NODES + SCAN_CHUNK - 1) / SCAN_CHUNK)   // 98

__global__ void scan_part_kernel() {
    __shared__ int sh[256];
    int b = blockIdx.x, t = threadIdx.x;
    int base = b * SCAN_CHUNK;
    int s = 0;
    for (int i = t; i < SCAN_CHUNK; i += 256) {
        int idx = base + i;
        s += (idx < N_NODES) ? g_deg[idx] : 0;
    }
    sh[t] = s; __syncthreads();
    for (int o = 128; o > 0; o >>= 1) {
        if (t < o) sh[t] += sh[t + o];
        __syncthreads();
    }
    if (t == 0) g_partial[b] = sh[0];
}

__global__ void scan_top_kernel() {   // blockDim = 128, SCAN_NB <= 128
    __shared__ int sh[128];
    int t = threadIdx.x;
    int v = (t < SCAN_NB) ? g_partial[t] : 0;
    sh[t] = v; __syncthreads();
    for (int o = 1; o < 128; o <<= 1) {
        int a = (t >= o) ? sh[t - o] : 0;
        __syncthreads();
        sh[t] += a;
        __syncthreads();
    }
    if (t < SCAN_NB) g_partial[t] = sh[t] - v;  // exclusive
}

__global__ void scan_final_kernel() {  // blockDim = 1024
    __shared__ int sh[SCAN_CHUNK];
    int b = blockIdx.x, t = threadIdx.x;
    int idx = b * SCAN_CHUNK + t;
    int v = (idx < N_NODES) ? g_deg[idx] : 0;
    sh[t] = v; __syncthreads();
    for (int o = 1; o < SCAN_CHUNK; o <<= 1) {
        int a = (t >= o) ? sh[t - o] : 0;
        __syncthreads();
        sh[t] += a;
        __syncthreads();
    }
    int incl = sh[t];
    int off = g_partial[b];
    if (idx < N_NODES) g_rowoff[idx] = off + incl - v;
    if (idx == N_NODES - 1) g_rowoff[N_NODES] = off + incl;
}

__global__ void fill_csr_kernel() {
    int e = blockIdx.x * blockDim.x + threadIdx.x;
    if (e < N_EDGES) {
        int d = g_dst[e];
        int pos = atomicAdd(&g_fill[d], 1);
        g_csr[g_rowoff[d] + pos] = g_src[e];
    }
}

// ---------------- GEMM1: m1[N,64] = x[N,128] @ W1[128,64] --------------------
// 256 threads: 16 col-groups (float4) x 16 rows = 16 rows/block
__global__ void __launch_bounds__(256) gemm1_kernel(const float* __restrict__ X,
                                                    const float* __restrict__ W) {
    __shared__ float4 Ws[IN_CH][16];          // 32 KB
    __shared__ float  Xs[IN_CH][17];          // transposed, padded (8.7 KB)
    int tid = threadIdx.x;
    const float4* W4 = (const float4*)W;
    #pragma unroll
    for (int i = tid; i < IN_CH * 16; i += 256) Ws[i >> 4][i & 15] = W4[i];

    int row0 = blockIdx.x * 16;
    const float* Xg = X + (size_t)row0 * IN_CH;
    for (int i = tid; i < 16 * IN_CH; i += 256) {
        int r = i >> 7, k = i & 127;
        Xs[k][r] = Xg[i];
    }
    __syncthreads();

    int cg = tid & 15;
    int rs = tid >> 4;
    float4 a0 = make_float4(0.f, 0.f, 0.f, 0.f);
    #pragma unroll 8
    for (int k = 0; k < IN_CH; ++k) {
        float4 w = Ws[k][cg];
        float x0 = Xs[k][rs];
        a0.x = fmaf(x0, w.x, a0.x); a0.y = fmaf(x0, w.y, a0.y);
        a0.z = fmaf(x0, w.z, a0.z); a0.w = fmaf(x0, w.w, a0.w);
    }
    float4* M4 = (float4*)(g_m1 + (size_t)row0 * HID);
    M4[rs * 16 + cg] = a0;
}

// ---------------- GEMM2: m2[N,32] = h[N,64] @ W2[64,32] ----------------------
// 256 threads: 8 col-groups (float4) x 32 row-slots (2 rows each) = 64 rows/block
__global__ void __launch_bounds__(256) gemm2_kernel(const float* __restrict__ W) {
    __shared__ float4 Ws[HID][8];            // 8 KB
    __shared__ float  Xs[HID][65];           // transposed, padded (16.6 KB)
    int tid = threadIdx.x;
    const float4* W4 = (const float4*)W;
    #pragma unroll
    for (int i = tid; i < HID * 8; i += 256) Ws[i >> 3][i & 7] = W4[i];

    int row0 = blockIdx.x * 64;
    for (int i = tid; i < 64 * HID; i += 256) {
        int r = i >> 6, k = i & 63;
        int row = row0 + r;
        Xs[k][r] = (row < N_NODES) ? g_h[(size_t)row * HID + k] : 0.f;
    }
    __syncthreads();

    int cg = tid & 7;
    int rs = tid >> 3;
    float4 a0 = make_float4(0.f, 0.f, 0.f, 0.f);
    float4 a1 = make_float4(0.f, 0.f, 0.f, 0.f);
    #pragma unroll 8
    for (int k = 0; k < HID; ++k) {
        float4 w = Ws[k][cg];
        float x0 = Xs[k][2 * rs];
        float x1 = Xs[k][2 * rs + 1];
        a0.x = fmaf(x0, w.x, a0.x); a0.y = fmaf(x0, w.y, a0.y);
        a0.z = fmaf(x0, w.z, a0.z); a0.w = fmaf(x0, w.w, a0.w);
        a1.x = fmaf(x1, w.x, a1.x); a1.y = fmaf(x1, w.y, a1.y);
        a1.z = fmaf(x1, w.z, a1.z); a1.w = fmaf(x1, w.w, a1.w);
    }
    int r0 = row0 + 2 * rs;
    if (r0 < N_NODES)
        ((float4*)(g_m2 + (size_t)r0 * OUT_CH))[cg] = a0;
    if (r0 + 1 < N_NODES)
        ((float4*)(g_m2 + (size_t)(r0 + 1) * OUT_CH))[cg] = a1;
}

// ---------------- aggregate layer 1: warp per node, 64 ch (float2/lane) ------
// h[d] = relu( dinv[d] * ( sum_s dinv[s]*m1[s] + dinv[d]*m1[d] ) + b1 )
__global__ void __launch_bounds__(256) aggregate1_kernel(const float* __restrict__ b1) {
    int warp = (blockIdx.x * blockDim.x + threadIdx.x) >> 5;
    if (warp >= N_NODES) return;
    int lane = threadIdx.x & 31;
    int node = warp;
    int beg = g_rowoff[node], end = g_rowoff[node + 1];
    float di = g_dinv[node];
    const float2* m2p = (const float2*)g_m1;

    float2 self = m2p[node * 32 + lane];
    float ax = di * self.x;
    float ay = di * self.y;

    int j = beg;
    for (; j + 4 <= end; j += 4) {
        int s0 = g_csr[j], s1 = g_csr[j + 1], s2 = g_csr[j + 2], s3 = g_csr[j + 3];
        float w0 = g_dinv[s0], w1 = g_dinv[s1], w2 = g_dinv[s2], w3 = g_dinv[s3];
        float2 v0 = m2p[s0 * 32 + lane];
        float2 v1 = m2p[s1 * 32 + lane];
        float2 v2 = m2p[s2 * 32 + lane];
        float2 v3 = m2p[s3 * 32 + lane];
        ax = fmaf(w0, v0.x, ax); ay = fmaf(w0, v0.y, ay);
        ax = fmaf(w1, v1.x, ax); ay = fmaf(w1, v1.y, ay);
        ax = fmaf(w2, v2.x, ax); ay = fmaf(w2, v2.y, ay);
        ax = fmaf(w3, v3.x, ax); ay = fmaf(w3, v3.y, ay);
    }
    for (; j < end; ++j) {
        int s = g_csr[j];
        float w = g_dinv[s];
        float2 v = m2p[s * 32 + lane];
        ax = fmaf(w, v.x, ax); ay = fmaf(w, v.y, ay);
    }
    float bx = b1[2 * lane], by = b1[2 * lane + 1];
    float2 out;
    out.x = fmaxf(fmaf(di, ax, bx), 0.f);
    out.y = fmaxf(fmaf(di, ay, by), 0.f);
    ((float2*)g_h)[node * 32 + lane] = out;
}

// ---------------- aggregate layer 2: warp per node, 32 ch (1 float/lane) -----
// out[d] = dinv[d] * ( sum_s dinv[s]*m2[s] + dinv[d]*m2[d] ) + b2
__global__ void __launch_bounds__(256) aggregate2_kernel(const float* __restrict__ b2,
                                                         float* __restrict__ out) {
    int warp = (blockIdx.x * blockDim.x + threadIdx.x) >> 5;
    if (warp >= N_NODES) return;
    int lane = threadIdx.x & 31;
    int node = warp;
    int beg = g_rowoff[node], end = g_rowoff[node + 1];
    float di = g_dinv[node];

    float acc = di * g_m2[node * 32 + lane];

    int j = beg;
    for (; j + 4 <= end; j += 4) {
        int s0 = g_csr[j], s1 = g_csr[j + 1], s2 = g_csr[j + 2], s3 = g_csr[j + 3];
        float w0 = g_dinv[s0], w1 = g_dinv[s1], w2 = g_dinv[s2], w3 = g_dinv[s3];
        float v0 = g_m2[s0 * 32 + lane];
        float v1 = g_m2[s1 * 32 + lane];
        float v2 = g_m2[s2 * 32 + lane];
        float v3 = g_m2[s3 * 32 + lane];
        acc = fmaf(w0, v0, acc);
        acc = fmaf(w1, v1, acc);
        acc = fmaf(w2, v2, acc);
        acc = fmaf(w3, v3, acc);
    }
    for (; j < end; ++j) {
        int s = g_csr[j];
        acc = fmaf(g_dinv[s], g_m2[s * 32 + lane], acc);
    }
    out[node * 32 + lane] = fmaf(di, acc, b2[lane]);
}

// ---------------- launch ------------------------------------------------------
extern "C" void kernel_launch(void* const* d_in, const int* in_sizes, int n_in,
                              void* d_out, int out_size) {
    const float* x  = (const float*)d_in[0];
    const int*   ei = (const int*)d_in[1];      // int32 view; sniffed at runtime
    const float* W1 = (const float*)d_in[2];
    const float* b1 = (const float*)d_in[3];
    const float* W2 = (const float*)d_in[4];
    const float* b2 = (const float*)d_in[5];
    float* out = (float*)d_out;

    (void)in_sizes; (void)n_in; (void)out_size;

    // Normalize edge index dtype
    detect_kernel<<<1, 32>>>(ei);
    convert_kernel<<<(N_EDGES + 255) / 256, 256>>>(ei);

    // CSR build
    zero_counts_kernel<<<(N_NODES + 255) / 256, 256>>>();
    count_deg_kernel<<<(N_EDGES + 255) / 256, 256>>>();
    dinv_kernel<<<(N_NODES + 255) / 256, 256>>>();
    scan_part_kernel<<<SCAN_NB, 256>>>();
    scan_top_kernel<<<1, 128>>>();
    scan_final_kernel<<<SCAN_NB, SCAN_CHUNK>>>();
    fill_csr_kernel<<<(N_EDGES + 255) / 256, 256>>>();

    // Layer 1
    gemm1_kernel<<<(N_NODES + 15) / 16, 256>>>(x, W1);
    aggregate1_kernel<<<(N_NODES * 32 + 255) / 256, 256>>>(b1);

    // Layer 2
    gemm2_kernel<<<(N_NODES + 63) / 64, 256>>>(W2);
    aggregate2_kernel<<<(N_NODES * 32 + 255) / 256, 256>>>(b2, out);
}

// round 4
// speedup vs baseline: 1.1057x; 1.1057x over previous
#include <cuda_runtime.h>
#include <cuda_bf16.h>
#include <stdint.h>

#define N_NODES 100000
#define N_EDGES 1600000
#define IN_CH   128
#define HID     64
#define OUT_CH  32

// ---------------- scratch (static device globals; no allocation) -------------
__device__ int   g_is64;
__device__ int   g_src[N_EDGES];
__device__ int   g_dst[N_EDGES];
__device__ int   g_deg[N_NODES];
__device__ float g_dinv[N_NODES];
__device__ int   g_rowoff[N_NODES + 1];
__device__ int   g_fill[N_NODES];
__device__ int   g_csr[N_EDGES];
__device__ int   g_partial[128];
__device__ float g_m1[(size_t)N_NODES * HID];
__device__ float g_h [(size_t)N_NODES * HID];
__device__ float g_m2[(size_t)N_NODES * OUT_CH];

// ---------------- packed fp32x2 FMA (Blackwell FFMA2) ------------------------
__device__ __forceinline__ void ffma2(float2& c, float2 a, float2 b) {
    unsigned long long A = *reinterpret_cast<unsigned long long*>(&a);
    unsigned long long B = *reinterpret_cast<unsigned long long*>(&b);
    unsigned long long C = *reinterpret_cast<unsigned long long*>(&c);
    asm("fma.rn.f32x2 %0, %1, %2, %3;" : "=l"(C) : "l"(A), "l"(B), "l"(C));
    c = *reinterpret_cast<float2*>(&C);
}

// ---------------- dtype sniff ------------------------------------------------
// int64 indices in [0, N_NODES) have zero high words; int32 random data doesn't.
__global__ void detect_kernel(const int* __restrict__ ei32) {
    int lane = threadIdx.x;
    int bad = 0;
    for (int e = lane; e < 256; e += 32)
        if (ei32[2 * e + 1] != 0) bad = 1;
    unsigned m = __ballot_sync(0xFFFFFFFFu, bad);
    if (lane == 0) g_is64 = (m == 0);
}

__global__ void zero_deg_kernel() {
    int i = blockIdx.x * blockDim.x + threadIdx.x;
    if (i < N_NODES) g_deg[i] = 0;
}

// convert + degree count in one pass
__global__ void convert_count_kernel(const int* __restrict__ ei32) {
    int e = blockIdx.x * blockDim.x + threadIdx.x;
    if (e >= N_EDGES) return;
    int s, d;
    if (g_is64) {
        s = ei32[2 * (size_t)e];
        d = ei32[2 * ((size_t)N_EDGES + e)];
    } else {
        s = ei32[e];
        d = ei32[(size_t)N_EDGES + e];
    }
    if ((unsigned)s >= N_NODES) s = 0;   // defensive; never on valid data
    if ((unsigned)d >= N_NODES) d = 0;
    g_src[e] = s;
    g_dst[e] = d;
    atomicAdd(&g_deg[d], 1);
}

// ---------------- exclusive scan of g_deg -> g_rowoff (+ dinv, fill=0) -------
#define SCAN_CHUNK 1024
#define SCAN_NB ((N_NODES + SCAN_CHUNK - 1) / SCAN_CHUNK)   // 98

__global__ void scan_part_kernel() {   // also computes dinv
    __shared__ int sh[256];
    int b = blockIdx.x, t = threadIdx.x;
    int base = b * SCAN_CHUNK;
    int s = 0;
    for (int i = t; i < SCAN_CHUNK; i += 256) {
        int idx = base + i;
        if (idx < N_NODES) {
            int dg = g_deg[idx];
            s += dg;
            g_dinv[idx] = rsqrtf((float)(dg + 1));   // +1 self-loop
        }
    }
    sh[t] = s; __syncthreads();
    for (int o = 128; o > 0; o >>= 1) {
        if (t < o) sh[t] += sh[t + o];
        __syncthreads();
    }
    if (t == 0) g_partial[b] = sh[0];
}

__global__ void scan_top_kernel() {   // blockDim = 128, SCAN_NB <= 128
    __shared__ int sh[128];
    int t = threadIdx.x;
    int v = (t < SCAN_NB) ? g_partial[t] : 0;
    sh[t] = v; __syncthreads();
    for (int o = 1; o < 128; o <<= 1) {
        int a = (t >= o) ? sh[t - o] : 0;
        __syncthreads();
        sh[t] += a;
        __syncthreads();
    }
    if (t < SCAN_NB) g_partial[t] = sh[t] - v;  // exclusive
}

__global__ void scan_final_kernel() {  // blockDim = 1024; also zero g_fill
    __shared__ int sh[SCAN_CHUNK];
    int b = blockIdx.x, t = threadIdx.x;
    int idx = b * SCAN_CHUNK + t;
    int v = (idx < N_NODES) ? g_deg[idx] : 0;
    sh[t] = v; __syncthreads();
    for (int o = 1; o < SCAN_CHUNK; o <<= 1) {
        int a = (t >= o) ? sh[t - o] : 0;
        __syncthreads();
        sh[t] += a;
        __syncthreads();
    }
    int incl = sh[t];
    int off = g_partial[b];
    if (idx < N_NODES) {
        g_rowoff[idx] = off + incl - v;
        g_fill[idx] = 0;
    }
    if (idx == N_NODES - 1) g_rowoff[N_NODES] = off + incl;
}

__global__ void fill_csr_kernel() {
    int e = blockIdx.x * blockDim.x + threadIdx.x;
    if (e < N_EDGES) {
        int d = g_dst[e];
        int pos = atomicAdd(&g_fill[d], 1);
        g_csr[g_rowoff[d] + pos] = g_src[e];
    }
}

// ---------------- GEMM1: m1[N,64] = x[N,128] @ W1[128,64] --------------------
// 256 threads, 32 rows/block: 16 col-groups (float4) x 16 slots x 2 rows/thread
__global__ void __launch_bounds__(256) gemm1_kernel(const float* __restrict__ X,
                                                    const float* __restrict__ W) {
    __shared__ float4 Ws[IN_CH][16];     // 32 KB
    __shared__ float  Xs[32][IN_CH];     // 16 KB row-major (total = 48 KB)
    int tid = threadIdx.x;
    const float4* W4 = (const float4*)W;
    #pragma unroll
    for (int i = tid; i < IN_CH * 16; i += 256) Ws[i >> 4][i & 15] = W4[i];

    int row0 = blockIdx.x * 32;
    const float4* Xg = (const float4*)(X + (size_t)row0 * IN_CH);
    float4* Xs4 = (float4*)Xs;
    #pragma unroll
    for (int i = tid; i < 32 * IN_CH / 4; i += 256) Xs4[i] = Xg[i];
    __syncthreads();

    int cg = tid & 15;
    int rs = tid >> 4;
    const float* x0p = Xs[2 * rs];
    const float* x1p = Xs[2 * rs + 1];
    float2 a0xy = {0.f, 0.f}, a0zw = {0.f, 0.f};
    float2 a1xy = {0.f, 0.f}, a1zw = {0.f, 0.f};
    #pragma unroll 4
    for (int k = 0; k < IN_CH; ++k) {
        float4 w = Ws[k][cg];
        float x0 = x0p[k], x1 = x1p[k];
        ffma2(a0xy, make_float2(w.x, w.y), make_float2(x0, x0));
        ffma2(a0zw, make_float2(w.z, w.w), make_float2(x0, x0));
        ffma2(a1xy, make_float2(w.x, w.y), make_float2(x1, x1));
        ffma2(a1zw, make_float2(w.z, w.w), make_float2(x1, x1));
    }
    float4* M4 = (float4*)(g_m1 + (size_t)row0 * HID);
    M4[(2 * rs) * 16 + cg]     = make_float4(a0xy.x, a0xy.y, a0zw.x, a0zw.y);
    M4[(2 * rs + 1) * 16 + cg] = make_float4(a1xy.x, a1xy.y, a1zw.x, a1zw.y);
}

// ---------------- GEMM2: m2[N,32] = h[N,64] @ W2[64,32] ----------------------
// 256 threads, 64 rows/block: 8 col-groups x 32 slots x 2 rows/thread
__global__ void __launch_bounds__(256) gemm2_kernel(const float* __restrict__ W) {
    __shared__ float4 Ws[HID][8];        // 8 KB
    __shared__ float  Xs[64][HID];       // 16 KB row-major
    int tid = threadIdx.x;
    const float4* W4 = (const float4*)W;
    #pragma unroll
    for (int i = tid; i < HID * 8; i += 256) Ws[i >> 3][i & 7] = W4[i];

    int row0 = blockIdx.x * 64;
    float4* Xs4 = (float4*)Xs;
    const float4* Hg = (const float4*)(g_h + (size_t)row0 * HID);
    #pragma unroll
    for (int i = tid; i < 64 * HID / 4; i += 256) {
        int row = row0 + (i >> 4);
        Xs4[i] = (row < N_NODES) ? Hg[i] : make_float4(0.f, 0.f, 0.f, 0.f);
    }
    __syncthreads();

    int cg = tid & 7;
    int rs = tid >> 3;
    const float* x0p = Xs[2 * rs];
    const float* x1p = Xs[2 * rs + 1];
    float2 a0xy = {0.f, 0.f}, a0zw = {0.f, 0.f};
    float2 a1xy = {0.f, 0.f}, a1zw = {0.f, 0.f};
    #pragma unroll 4
    for (int k = 0; k < HID; ++k) {
        float4 w = Ws[k][cg];
        float x0 = x0p[k], x1 = x1p[k];
        ffma2(a0xy, make_float2(w.x, w.y), make_float2(x0, x0));
        ffma2(a0zw, make_float2(w.z, w.w), make_float2(x0, x0));
        ffma2(a1xy, make_float2(w.x, w.y), make_float2(x1, x1));
        ffma2(a1zw, make_float2(w.z, w.w), make_float2(x1, x1));
    }
    int r0 = row0 + 2 * rs;
    if (r0 < N_NODES)
        ((float4*)(g_m2 + (size_t)r0 * OUT_CH))[cg] =
            make_float4(a0xy.x, a0xy.y, a0zw.x, a0zw.y);
    if (r0 + 1 < N_NODES)
        ((float4*)(g_m2 + (size_t)(r0 + 1) * OUT_CH))[cg] =
            make_float4(a1xy.x, a1xy.y, a1zw.x, a1zw.y);
}

// ---------------- aggregate layer 1: warp per node, 64 ch (float2/lane) ------
// h[d] = relu( dinv[d] * ( sum_s dinv[s]*m1[s] + dinv[d]*m1[d] ) + b1 )
__global__ void __launch_bounds__(256) aggregate1_kernel(const float* __restrict__ b1) {
    int warp = (blockIdx.x * blockDim.x + threadIdx.x) >> 5;
    if (warp >= N_NODES) return;
    int lane = threadIdx.x & 31;
    int node = warp;
    int beg = g_rowoff[node], end = g_rowoff[node + 1];
    float di = g_dinv[node];
    const float2* m2p = (const float2*)g_m1;

    float2 self = m2p[node * 32 + lane];
    float2 acc = make_float2(di * self.x, di * self.y);

    int j = beg;
    for (; j + 8 <= end; j += 8) {
        int s0 = g_csr[j],     s1 = g_csr[j + 1], s2 = g_csr[j + 2], s3 = g_csr[j + 3];
        int s4 = g_csr[j + 4], s5 = g_csr[j + 5], s6 = g_csr[j + 6], s7 = g_csr[j + 7];
        float w0 = g_dinv[s0], w1 = g_dinv[s1], w2 = g_dinv[s2], w3 = g_dinv[s3];
        float w4 = g_dinv[s4], w5 = g_dinv[s5], w6 = g_dinv[s6], w7 = g_dinv[s7];
        float2 v0 = m2p[s0 * 32 + lane], v1 = m2p[s1 * 32 + lane];
        float2 v2 = m2p[s2 * 32 + lane], v3 = m2p[s3 * 32 + lane];
        float2 v4 = m2p[s4 * 32 + lane], v5 = m2p[s5 * 32 + lane];
        float2 v6 = m2p[s6 * 32 + lane], v7 = m2p[s7 * 32 + lane];
        ffma2(acc, v0, make_float2(w0, w0));
        ffma2(acc, v1, make_float2(w1, w1));
        ffma2(acc, v2, make_float2(w2, w2));
        ffma2(acc, v3, make_float2(w3, w3));
        ffma2(acc, v4, make_float2(w4, w4));
        ffma2(acc, v5, make_float2(w5, w5));
        ffma2(acc, v6, make_float2(w6, w6));
        ffma2(acc, v7, make_float2(w7, w7));
    }
    for (; j < end; ++j) {
        int s = g_csr[j];
        float w = g_dinv[s];
        float2 v = m2p[s * 32 + lane];
        ffma2(acc, v, make_float2(w, w));
    }
    float2 b = make_float2(b1[2 * lane], b1[2 * lane + 1]);
    ffma2(b, acc, make_float2(di, di));   // b = di*acc + bias
    float2 out;
    out.x = fmaxf(b.x, 0.f);
    out.y = fmaxf(b.y, 0.f);
    ((float2*)g_h)[node * 32 + lane] = out;
}

// ---------------- aggregate layer 2: warp per node, 32 ch (1 float/lane) -----
// out[d] = dinv[d] * ( sum_s dinv[s]*m2[s] + dinv[d]*m2[d] ) + b2
__global__ void __launch_bounds__(256) aggregate2_kernel(const float* __restrict__ b2,
                                                         float* __restrict__ out) {
    int warp = (blockIdx.x * blockDim.x + threadIdx.x) >> 5;
    if (warp >= N_NODES) return;
    int lane = threadIdx.x & 31;
    int node = warp;
    int beg = g_rowoff[node], end = g_rowoff[node + 1];
    float di = g_dinv[node];

    // two pair-accumulators (edge pairs packed into f32x2 lanes)
    float2 accA = make_float2(di * g_m2[node * 32 + lane], 0.f);
    float2 accB = make_float2(0.f, 0.f);

    int j = beg;
    for (; j + 8 <= end; j += 8) {
        int s0 = g_csr[j],     s1 = g_csr[j + 1], s2 = g_csr[j + 2], s3 = g_csr[j + 3];
        int s4 = g_csr[j + 4], s5 = g_csr[j + 5], s6 = g_csr[j + 6], s7 = g_csr[j + 7];
        float w0 = g_dinv[s0], w1 = g_dinv[s1], w2 = g_dinv[s2], w3 = g_dinv[s3];
        float w4 = g_dinv[s4], w5 = g_dinv[s5], w6 = g_dinv[s6], w7 = g_dinv[s7];
        float v0 = g_m2[s0 * 32 + lane], v1 = g_m2[s1 * 32 + lane];
        float v2 = g_m2[s2 * 32 + lane], v3 = g_m2[s3 * 32 + lane];
        float v4 = g_m2[s4 * 32 + lane], v5 = g_m2[s5 * 32 + lane];
        float v6 = g_m2[s6 * 32 + lane], v7 = g_m2[s7 * 32 + lane];
        ffma2(accA, make_float2(v0, v1), make_float2(w0, w1));
        ffma2(accB, make_float2(v2, v3), make_float2(w2, w3));
        ffma2(accA, make_float2(v4, v5), make_float2(w4, w5));
        ffma2(accB, make_float2(v6, v7), make_float2(w6, w7));
    }
    for (; j < end; ++j) {
        int s = g_csr[j];
        accA.x = fmaf(g_dinv[s], g_m2[s * 32 + lane], accA.x);
    }
    float acc = (accA.x + accA.y) + (accB.x + accB.y);
    out[node * 32 + lane] = fmaf(di, acc, b2[lane]);
}

// ---------------- launch ------------------------------------------------------
extern "C" void kernel_launch(void* const* d_in, const int* in_sizes, int n_in,
                              void* d_out, int out_size) {
    const float* x  = (const float*)d_in[0];
    const int*   ei = (const int*)d_in[1];      // int32 view; dtype sniffed
    const float* W1 = (const float*)d_in[2];
    const float* b1 = (const float*)d_in[3];
    const float* W2 = (const float*)d_in[4];
    const float* b2 = (const float*)d_in[5];
    float* out = (float*)d_out;

    (void)in_sizes; (void)n_in; (void)out_size;

    // CSR build
    detect_kernel<<<1, 32>>>(ei);
    zero_deg_kernel<<<(N_NODES + 255) / 256, 256>>>();
    convert_count_kernel<<<(N_EDGES + 255) / 256, 256>>>(ei);
    scan_part_kernel<<<SCAN_NB, 256>>>();
    scan_top_kernel<<<1, 128>>>();
    scan_final_kernel<<<SCAN_NB, SCAN_CHUNK>>>();
    fill_csr_kernel<<<(N_EDGES + 255) / 256, 256>>>();

    // Layer 1
    gemm1_kernel<<<N_NODES / 32, 256>>>(x, W1);
    aggregate1_kernel<<<(N_NODES * 32 + 255) / 256, 256>>>(b1);

    // Layer 2
    gemm2_kernel<<<(N_NODES + 63) / 64, 256>>>(W2);
    aggregate2_kernel<<<(N_NODES * 32 + 255) / 256, 256>>>(b2, out);
}

// round 5
// speedup vs baseline: 1.1147x; 1.0082x over previous
#include <cuda_runtime.h>
#include <cuda_bf16.h>
#include <stdint.h>

#define N_NODES 100000
#define N_EDGES 1600000
#define IN_CH   128
#define HID     64
#define OUT_CH  32

// gemm1 covers 3125 blocks of 32 rows; split between fusedA / fusedB
#define G1A_BLOCKS 1250
#define G1B_BLOCKS 1875
#define EDGE_BLOCKS 1563           // 1563 * 1024 edges >= N_EDGES

// ---------------- scratch (static device globals; no allocation) -------------
__device__ int   g_is64;
__device__ int   g_deg[N_NODES];
__device__ float g_dinv[N_NODES];
__device__ int   g_rowoff[N_NODES + 1];
__device__ int   g_fill[N_NODES];
__device__ int   g_csr[N_EDGES];
__device__ int   g_partial[128];
__device__ float g_m1[(size_t)N_NODES * HID];
__device__ float g_h [(size_t)N_NODES * HID];
__device__ float g_m2[(size_t)N_NODES * OUT_CH];

// ---------------- packed fp32x2 FMA (Blackwell FFMA2) ------------------------
__device__ __forceinline__ void ffma2(float2& c, float2 a, float2 b) {
    unsigned long long A = *reinterpret_cast<unsigned long long*>(&a);
    unsigned long long B = *reinterpret_cast<unsigned long long*>(&b);
    unsigned long long C = *reinterpret_cast<unsigned long long*>(&c);
    asm("fma.rn.f32x2 %0, %1, %2, %3;" : "=l"(C) : "l"(A), "l"(B), "l"(C));
    c = *reinterpret_cast<float2*>(&C);
}

// ---------------- edge decode (dtype-agnostic) -------------------------------
__device__ __forceinline__ int load_dst(const int* __restrict__ ei, int e, int is64) {
    int d = is64 ? ei[2 * ((size_t)N_EDGES + e)] : ei[(size_t)N_EDGES + e];
    return ((unsigned)d < N_NODES) ? d : 0;
}
__device__ __forceinline__ int load_src(const int* __restrict__ ei, int e, int is64) {
    int s = is64 ? ei[2 * (size_t)e] : ei[e];
    return ((unsigned)s < N_NODES) ? s : 0;
}

// ---------------- dtype sniff ------------------------------------------------
// int64 indices in [0, N_NODES) have zero high words; int32 random data doesn't.
__global__ void detect_kernel(const int* __restrict__ ei32) {
    int lane = threadIdx.x;
    int bad = 0;
    for (int e = lane; e < 256; e += 32)
        if (ei32[2 * e + 1] != 0) bad = 1;
    unsigned m = __ballot_sync(0xFFFFFFFFu, bad);
    if (lane == 0) g_is64 = (m == 0);
}

__global__ void zero_deg_kernel() {
    int i = blockIdx.x * blockDim.x + threadIdx.x;
    if (i < N_NODES) g_deg[i] = 0;
}

// ---------------- GEMM1 body (shared by fusedA / fusedB) ---------------------
__device__ __forceinline__ void gemm1_body(int row0,
                                           const float* __restrict__ X,
                                           const float* __restrict__ W,
                                           float4 (*Ws)[16],
                                           float (*Xs)[IN_CH]) {
    int tid = threadIdx.x;
    const float4* W4 = (const float4*)W;
    #pragma unroll
    for (int i = tid; i < IN_CH * 16; i += 256) Ws[i >> 4][i & 15] = W4[i];

    const float4* Xg = (const float4*)(X + (size_t)row0 * IN_CH);
    float4* Xs4 = (float4*)Xs;
    #pragma unroll
    for (int i = tid; i < 32 * IN_CH / 4; i += 256) Xs4[i] = Xg[i];
    __syncthreads();

    int cg = tid & 15;
    int rs = tid >> 4;
    const float* x0p = Xs[2 * rs];
    const float* x1p = Xs[2 * rs + 1];
    float2 a0xy = {0.f, 0.f}, a0zw = {0.f, 0.f};
    float2 a1xy = {0.f, 0.f}, a1zw = {0.f, 0.f};
    #pragma unroll 4
    for (int k = 0; k < IN_CH; ++k) {
        float4 w = Ws[k][cg];
        float x0 = x0p[k], x1 = x1p[k];
        ffma2(a0xy, make_float2(w.x, w.y), make_float2(x0, x0));
        ffma2(a0zw, make_float2(w.z, w.w), make_float2(x0, x0));
        ffma2(a1xy, make_float2(w.x, w.y), make_float2(x1, x1));
        ffma2(a1zw, make_float2(w.z, w.w), make_float2(x1, x1));
    }
    float4* M4 = (float4*)(g_m1 + (size_t)row0 * HID);
    M4[(2 * rs) * 16 + cg]     = make_float4(a0xy.x, a0xy.y, a0zw.x, a0zw.y);
    M4[(2 * rs + 1) * 16 + cg] = make_float4(a1xy.x, a1xy.y, a1zw.x, a1zw.y);
}

// ---------------- fusedA: gemm1 rows [0, 40000) ⊕ degree count ---------------
__global__ void __launch_bounds__(256) fusedA_kernel(const float* __restrict__ X,
                                                     const float* __restrict__ W1,
                                                     const int* __restrict__ ei) {
    __shared__ float4 Ws[IN_CH][16];
    __shared__ float  Xs[32][IN_CH];
    int bid = blockIdx.x;
    if ((bid & 1) == 0) {
        int g = bid >> 1;
        if (g >= G1A_BLOCKS) return;
        gemm1_body(g * 32, X, W1, Ws, Xs);
    } else {
        int eb = bid >> 1;                 // < EDGE_BLOCKS
        int is64 = g_is64;
        int base = eb * 1024 + threadIdx.x;
        #pragma unroll
        for (int i = 0; i < 4; ++i) {
            int e = base + i * 256;
            if (e < N_EDGES) atomicAdd(&g_deg[load_dst(ei, e, is64)], 1);
        }
    }
}

// ---------------- fusedB: gemm1 rows [40000, 100000) ⊕ CSR fill --------------
__global__ void __launch_bounds__(256) fusedB_kernel(const float* __restrict__ X,
                                                     const float* __restrict__ W1,
                                                     const int* __restrict__ ei) {
    __shared__ float4 Ws[IN_CH][16];
    __shared__ float  Xs[32][IN_CH];
    int bid = blockIdx.x;
    if ((bid & 1) == 0) {
        int g = (bid >> 1) + G1A_BLOCKS;   // rows 40000..99999
        gemm1_body(g * 32, X, W1, Ws, Xs);
    } else {
        int eb = bid >> 1;
        if (eb >= EDGE_BLOCKS) return;
        int is64 = g_is64;
        int base = eb * 1024 + threadIdx.x;
        #pragma unroll
        for (int i = 0; i < 4; ++i) {
            int e = base + i * 256;
            if (e < N_EDGES) {
                int d = load_dst(ei, e, is64);
                int s = load_src(ei, e, is64);
                int pos = atomicAdd(&g_fill[d], 1);
                g_csr[g_rowoff[d] + pos] = s;
            }
        }
    }
}

// ---------------- exclusive scan of g_deg -> g_rowoff (+ dinv, fill=0) -------
#define SCAN_CHUNK 1024
#define SCAN_NB ((N_NODES + SCAN_CHUNK - 1) / SCAN_CHUNK)   // 98

__global__ void scan_part_kernel() {   // also computes dinv
    __shared__ int sh[256];
    int b = blockIdx.x, t = threadIdx.x;
    int base = b * SCAN_CHUNK;
    int s = 0;
    for (int i = t; i < SCAN_CHUNK; i += 256) {
        int idx = base + i;
        if (idx < N_NODES) {
            int dg = g_deg[idx];
            s += dg;
            g_dinv[idx] = rsqrtf((float)(dg + 1));   // +1 self-loop
        }
    }
    sh[t] = s; __syncthreads();
    for (int o = 128; o > 0; o >>= 1) {
        if (t < o) sh[t] += sh[t + o];
        __syncthreads();
    }
    if (t == 0) g_partial[b] = sh[0];
}

__global__ void scan_top_kernel() {   // blockDim = 128, SCAN_NB <= 128
    __shared__ int sh[128];
    int t = threadIdx.x;
    int v = (t < SCAN_NB) ? g_partial[t] : 0;
    sh[t] = v; __syncthreads();
    for (int o = 1; o < 128; o <<= 1) {
        int a = (t >= o) ? sh[t - o] : 0;
        __syncthreads();
        sh[t] += a;
        __syncthreads();
    }
    if (t < SCAN_NB) g_partial[t] = sh[t] - v;  // exclusive
}

__global__ void scan_final_kernel() {  // blockDim = 1024; also zero g_fill
    __shared__ int sh[SCAN_CHUNK];
    int b = blockIdx.x, t = threadIdx.x;
    int idx = b * SCAN_CHUNK + t;
    int v = (idx < N_NODES) ? g_deg[idx] : 0;
    sh[t] = v; __syncthreads();
    for (int o = 1; o < SCAN_CHUNK; o <<= 1) {
        int a = (t >= o) ? sh[t - o] : 0;
        __syncthreads();
        sh[t] += a;
        __syncthreads();
    }
    int incl = sh[t];
    int off = g_partial[b];
    if (idx < N_NODES) {
        g_rowoff[idx] = off + incl - v;
        g_fill[idx] = 0;
    }
    if (idx == N_NODES - 1) g_rowoff[N_NODES] = off + incl;
}

// ---------------- GEMM2: m2[N,32] = h[N,64] @ W2[64,32] ----------------------
__global__ void __launch_bounds__(256) gemm2_kernel(const float* __restrict__ W) {
    __shared__ float4 Ws[HID][8];        // 8 KB
    __shared__ float  Xs[64][HID];       // 16 KB
    int tid = threadIdx.x;
    const float4* W4 = (const float4*)W;
    #pragma unroll
    for (int i = tid; i < HID * 8; i += 256) Ws[i >> 3][i & 7] = W4[i];

    int row0 = blockIdx.x * 64;
    float4* Xs4 = (float4*)Xs;
    const float4* Hg = (const float4*)(g_h + (size_t)row0 * HID);
    #pragma unroll
    for (int i = tid; i < 64 * HID / 4; i += 256) {
        int row = row0 + (i >> 4);
        Xs4[i] = (row < N_NODES) ? Hg[i] : make_float4(0.f, 0.f, 0.f, 0.f);
    }
    __syncthreads();

    int cg = tid & 7;
    int rs = tid >> 3;
    const float* x0p = Xs[2 * rs];
    const float* x1p = Xs[2 * rs + 1];
    float2 a0xy = {0.f, 0.f}, a0zw = {0.f, 0.f};
    float2 a1xy = {0.f, 0.f}, a1zw = {0.f, 0.f};
    #pragma unroll 4
    for (int k = 0; k < HID; ++k) {
        float4 w = Ws[k][cg];
        float x0 = x0p[k], x1 = x1p[k];
        ffma2(a0xy, make_float2(w.x, w.y), make_float2(x0, x0));
        ffma2(a0zw, make_float2(w.z, w.w), make_float2(x0, x0));
        ffma2(a1xy, make_float2(w.x, w.y), make_float2(x1, x1));
        ffma2(a1zw, make_float2(w.z, w.w), make_float2(x1, x1));
    }
    int r0 = row0 + 2 * rs;
    if (r0 < N_NODES)
        ((float4*)(g_m2 + (size_t)r0 * OUT_CH))[cg] =
            make_float4(a0xy.x, a0xy.y, a0zw.x, a0zw.y);
    if (r0 + 1 < N_NODES)
        ((float4*)(g_m2 + (size_t)(r0 + 1) * OUT_CH))[cg] =
            make_float4(a1xy.x, a1xy.y, a1zw.x, a1zw.y);
}

// ---------------- aggregate layer 1: warp per node, 64 ch (float2/lane) ------
__global__ void __launch_bounds__(256) aggregate1_kernel(const float* __restrict__ b1) {
    int warp = (blockIdx.x * blockDim.x + threadIdx.x) >> 5;
    if (warp >= N_NODES) return;
    int lane = threadIdx.x & 31;
    int node = warp;
    int beg = g_rowoff[node], end = g_rowoff[node + 1];
    float di = g_dinv[node];
    const float2* m2p = (const float2*)g_m1;

    float2 self = m2p[node * 32 + lane];
    float2 acc = make_float2(di * self.x, di * self.y);

    int j = beg;
    for (; j + 8 <= end; j += 8) {
        int s0 = g_csr[j],     s1 = g_csr[j + 1], s2 = g_csr[j + 2], s3 = g_csr[j + 3];
        int s4 = g_csr[j + 4], s5 = g_csr[j + 5], s6 = g_csr[j + 6], s7 = g_csr[j + 7];
        float w0 = g_dinv[s0], w1 = g_dinv[s1], w2 = g_dinv[s2], w3 = g_dinv[s3];
        float w4 = g_dinv[s4], w5 = g_dinv[s5], w6 = g_dinv[s6], w7 = g_dinv[s7];
        float2 v0 = m2p[s0 * 32 + lane], v1 = m2p[s1 * 32 + lane];
        float2 v2 = m2p[s2 * 32 + lane], v3 = m2p[s3 * 32 + lane];
        float2 v4 = m2p[s4 * 32 + lane], v5 = m2p[s5 * 32 + lane];
        float2 v6 = m2p[s6 * 32 + lane], v7 = m2p[s7 * 32 + lane];
        ffma2(acc, v0, make_float2(w0, w0));
        ffma2(acc, v1, make_float2(w1, w1));
        ffma2(acc, v2, make_float2(w2, w2));
        ffma2(acc, v3, make_float2(w3, w3));
        ffma2(acc, v4, make_float2(w4, w4));
        ffma2(acc, v5, make_float2(w5, w5));
        ffma2(acc, v6, make_float2(w6, w6));
        ffma2(acc, v7, make_float2(w7, w7));
    }
    for (; j < end; ++j) {
        int s = g_csr[j];
        float w = g_dinv[s];
        float2 v = m2p[s * 32 + lane];
        ffma2(acc, v, make_float2(w, w));
    }
    float2 b = make_float2(b1[2 * lane], b1[2 * lane + 1]);
    ffma2(b, acc, make_float2(di, di));   // b = di*acc + bias
    float2 out;
    out.x = fmaxf(b.x, 0.f);
    out.y = fmaxf(b.y, 0.f);
    ((float2*)g_h)[node * 32 + lane] = out;
}

// ---------------- aggregate layer 2: warp per node, 32 ch (1 float/lane) -----
__global__ void __launch_bounds__(256) aggregate2_kernel(const float* __restrict__ b2,
                                                         float* __restrict__ out) {
    int warp = (blockIdx.x * blockDim.x + threadIdx.x) >> 5;
    if (warp >= N_NODES) return;
    int lane = threadIdx.x & 31;
    int node = warp;
    int beg = g_rowoff[node], end = g_rowoff[node + 1];
    float di = g_dinv[node];

    float2 accA = make_float2(di * g_m2[node * 32 + lane], 0.f);
    float2 accB = make_float2(0.f, 0.f);

    int j = beg;
    for (; j + 8 <= end; j += 8) {
        int s0 = g_csr[j],     s1 = g_csr[j + 1], s2 = g_csr[j + 2], s3 = g_csr[j + 3];
        int s4 = g_csr[j + 4], s5 = g_csr[j + 5], s6 = g_csr[j + 6], s7 = g_csr[j + 7];
        float w0 = g_dinv[s0], w1 = g_dinv[s1], w2 = g_dinv[s2], w3 = g_dinv[s3];
        float w4 = g_dinv[s4], w5 = g_dinv[s5], w6 = g_dinv[s6], w7 = g_dinv[s7];
        float v0 = g_m2[s0 * 32 + lane], v1 = g_m2[s1 * 32 + lane];
        float v2 = g_m2[s2 * 32 + lane], v3 = g_m2[s3 * 32 + lane];
        float v4 = g_m2[s4 * 32 + lane], v5 = g_m2[s5 * 32 + lane];
        float v6 = g_m2[s6 * 32 + lane], v7 = g_m2[s7 * 32 + lane];
        ffma2(accA, make_float2(v0, v1), make_float2(w0, w1));
        ffma2(accB, make_float2(v2, v3), make_float2(w2, w3));
        ffma2(accA, make_float2(v4, v5), make_float2(w4, w5));
        ffma2(accB, make_float2(v6, v7), make_float2(w6, w7));
    }
    for (; j < end; ++j) {
        int s = g_csr[j];
        accA.x = fmaf(g_dinv[s], g_m2[s * 32 + lane], accA.x);
    }
    float acc = (accA.x + accA.y) + (accB.x + accB.y);
    out[node * 32 + lane] = fmaf(di, acc, b2[lane]);
}

// ---------------- launch ------------------------------------------------------
extern "C" void kernel_launch(void* const* d_in, const int* in_sizes, int n_in,
                              void* d_out, int out_size) {
    const float* x  = (const float*)d_in[0];
    const int*   ei = (const int*)d_in[1];      // int32 view; dtype sniffed
    const float* W1 = (const float*)d_in[2];
    const float* b1 = (const float*)d_in[3];
    const float* W2 = (const float*)d_in[4];
    const float* b2 = (const float*)d_in[5];
    float* out = (float*)d_out;

    (void)in_sizes; (void)n_in; (void)out_size;

    detect_kernel<<<1, 32>>>(ei);
    zero_deg_kernel<<<(N_NODES + 255) / 256, 256>>>();

    // gemm1 (part 1) overlapped with degree counting
    fusedA_kernel<<<2 * EDGE_BLOCKS, 256>>>(x, W1, ei);

    scan_part_kernel<<<SCAN_NB, 256>>>();
    scan_top_kernel<<<1, 128>>>();
    scan_final_kernel<<<SCAN_NB, SCAN_CHUNK>>>();

    // gemm1 (part 2) overlapped with CSR fill
    fusedB_kernel<<<2 * G1B_BLOCKS, 256>>>(x, W1, ei);

    aggregate1_kernel<<<(N_NODES * 32 + 255) / 256, 256>>>(b1);
    gemm2_kernel<<<(N_NODES + 63) / 64, 256>>>(W2);
    aggregate2_kernel<<<(N_NODES * 32 + 255) / 256, 256>>>(b2, out);
}